// round 14
// baseline (speedup 1.0000x reference)
#include <cuda_runtime.h>
#include <cuda_bf16.h>
#include <stdint.h>

// SelectiveLinear: out[b,:] = X[b,:] @ W[idx[b]] + bias[idx[b]]
// B=2048, IN=512, OUT=512, H=16.
// R14: FUSED 3-term split-bf16 GEMM. One block computes Xhi*Whi + Xlo*Whi +
// Xhi*Wlo over full K for its 64x128 tile: operand planes loaded once per
// chunk serve 3 MMA passes (compute/smem-byte 1.5x R10's split design).
// No split-K -> direct store + bias (no atomics, no output zeroing).
// Warp-level fragment math identical to R10 (proven): 4 warps 2x2, tile 32x64.

#define IN_DIM  512
#define OUT_DIM 512
#define NHEADS  16
#define MAXB    2048
#define KPACK   1024            // g_A row: [hi(512) | lo(512)] bf16
#define NCHUNK  32              // k16 chunks covering K=512
#define A_STRIDE_B 48           // A plane row stride: 32B data + 16B pad
#define B_STRIDE_B 272          // B plane row stride: 256B data + 16B pad
#define A_PL_B  (64 * A_STRIDE_B)     // 3072
#define B_PL_B  (16 * B_STRIDE_B)     // 4352
#define OFF_AHI 0
#define OFF_ALO (A_PL_B)              // 3072
#define OFF_BHI (2 * A_PL_B)          // 6144
#define OFF_BLO (2 * A_PL_B + B_PL_B) // 10496
#define STAGE_B (2 * A_PL_B + 2 * B_PL_B)  // 14848; 3 stages = 44544 < 48K

__device__ int g_rows[MAXB];
__device__ int g_off[NHEADS + 1];
__device__ int g_is64;
__device__ __align__(256) __nv_bfloat16 g_A[(size_t)MAXB * KPACK];                   // 4MB
__device__ __align__(256) __nv_bfloat16 g_Bw[(size_t)NHEADS * 2 * IN_DIM * OUT_DIM]; // 16MB

__device__ __forceinline__ uint32_t smem_u32(const void* p) {
    uint32_t a;
    asm("{ .reg .u64 t; cvta.to.shared.u64 t, %1; cvt.u32.u64 %0, t; }"
        : "=r"(a) : "l"(p));
    return a;
}
__device__ __forceinline__ void cpasync16(uint32_t dst, const void* src) {
    asm volatile("cp.async.cg.shared.global [%0], [%1], 16;" :: "r"(dst), "l"(src) : "memory");
}
#define CP_COMMIT() asm volatile("cp.async.commit_group;" ::: "memory")
#define CP_WAIT0()  asm volatile("cp.async.wait_group 0;" ::: "memory")
#define CP_WAIT1()  asm volatile("cp.async.wait_group 1;" ::: "memory")

__device__ __forceinline__ int load_idx(const int* __restrict__ w, int b, int is64) {
    return w[is64 ? (b << 1) : b];
}

// ---------------------------------------------------------------------------
// Kernel 1: prep (no output zeroing needed anymore).
//   bx == 0            : idx dtype sniff + bucket-by-head
//   bx in [1, XB]      : X -> bf16 hi|lo (at original row)
//   bx in (XB, XB+512] : W -> bf16 hi|lo  [h][sel][k][n]
// ---------------------------------------------------------------------------
__global__ __launch_bounds__(256)
void prep(const float* __restrict__ X, const int* __restrict__ idx_w,
          const float* __restrict__ W, int Bn) {
    const int bx = blockIdx.x;
    const int tid = threadIdx.x;
    const int XB = (Bn + 7) / 8;

    if (bx == 0) {
        __shared__ int s_not;
        __shared__ int s_cnt[NHEADS];
        __shared__ int s_base[NHEADS];
        if (tid == 0) s_not = 0;
        __syncthreads();
        for (int i = tid; i < Bn; i += 256) {
            int v = idx_w[i];
            if (i & 1) { if (v != 0) s_not = 1; }
            else       { if (v < 0 || v >= NHEADS) s_not = 1; }
        }
        __syncthreads();
        const int is64 = s_not ? 0 : 1;
        if (tid == 0) g_is64 = is64;
        if (tid < NHEADS) s_cnt[tid] = 0;
        __syncthreads();
        for (int b = tid; b < Bn; b += 256)
            atomicAdd(&s_cnt[load_idx(idx_w, b, is64) & (NHEADS - 1)], 1);
        __syncthreads();
        if (tid == 0) {
            int acc = 0;
            for (int h = 0; h < NHEADS; h++) { g_off[h] = acc; s_base[h] = acc; acc += s_cnt[h]; }
            g_off[NHEADS] = acc;
        }
        __syncthreads();
        for (int b = tid; b < Bn; b += 256) {
            int h = load_idx(idx_w, b, is64) & (NHEADS - 1);
            g_rows[atomicAdd(&s_base[h], 1)] = b;
        }
    } else if (bx <= XB) {
        int p = (bx - 1) * 8 + (tid >> 5);
        int l = tid & 31;
        if (p >= Bn) return;
        const float4* xr = (const float4*)(X + (size_t)p * IN_DIM);
        union { __nv_bfloat16 h[16]; uint4 u[2]; } hi, lo;
#pragma unroll
        for (int q = 0; q < 4; q++) {
            float4 v = xr[l * 4 + q];
            float f[4] = {v.x, v.y, v.z, v.w};
#pragma unroll
            for (int e = 0; e < 4; e++) {
                __nv_bfloat16 hv = __float2bfloat16(f[e]);
                hi.h[q * 4 + e] = hv;
                lo.h[q * 4 + e] = __float2bfloat16(f[e] - __bfloat162float(hv));
            }
        }
        uint4* dh = (uint4*)(g_A + (size_t)p * KPACK + l * 16);
        dh[0] = hi.u[0]; dh[1] = hi.u[1];
        uint4* dl = (uint4*)(g_A + (size_t)p * KPACK + 512 + l * 16);
        dl[0] = lo.u[0]; dl[1] = lo.u[1];
    } else {
        const int wb = bx - 1 - XB;
        const int total = NHEADS * IN_DIM * (OUT_DIM / 4);
#pragma unroll
        for (int i = 0; i < 8; i++) {
            int id = wb * 2048 + i * 256 + tid;
            if (id >= total) break;
            int h   = id / (IN_DIM * (OUT_DIM / 4));
            int rem = id % (IN_DIM * (OUT_DIM / 4));
            int k   = rem / (OUT_DIM / 4);
            int n4  = rem % (OUT_DIM / 4);
            float4 v = ((const float4*)W)[(size_t)id];
            float f[4] = {v.x, v.y, v.z, v.w};
            union { __nv_bfloat16 h[4]; uint2 u; } hi, lo;
#pragma unroll
            for (int e = 0; e < 4; e++) {
                __nv_bfloat16 hv = __float2bfloat16(f[e]);
                hi.h[e] = hv;
                lo.h[e] = __float2bfloat16(f[e] - __bfloat162float(hv));
            }
            size_t basehi = (((size_t)h * 2 + 0) * IN_DIM + k) * OUT_DIM + n4 * 4;
            size_t baselo = (((size_t)h * 2 + 1) * IN_DIM + k) * OUT_DIM + n4 * 4;
            *(uint2*)(g_Bw + basehi) = hi.u;
            *(uint2*)(g_Bw + baselo) = lo.u;
        }
    }
}

// ---------------------------------------------------------------------------
// Kernel 2: fused 3-term GEMM + tail echo.
// grid (4 n-tiles, ceil(Bn/64) m-slots, NHEADS+1), 128 threads (4 warps 2x2).
// Block tile M=64, N=128; warp tile 32x64; 32 chunks of k=16; each chunk
// loads Ahi|Alo|Bhi|Blo once, runs 3 MMA passes into one accumulator.
// 3-stage cp.async pipeline; direct-store epilogue with bias.
// ---------------------------------------------------------------------------
__global__ __launch_bounds__(128)
void gemm_mma(const float* __restrict__ bias, float* __restrict__ out, int Bn,
              const int* __restrict__ idx_w, float* __restrict__ tail, int mode) {
    const int z = blockIdx.z;
    if (z == NHEADS) {   // fused tail echo
        if (blockIdx.x == 0 && blockIdx.y == 0 && tail != nullptr) {
            const int is64 = g_is64;
            for (int b = threadIdx.x; b < Bn; b += 128) {
                int v = load_idx(idx_w, b, is64) & (NHEADS - 1);
                if (mode == 1) tail[b] = (float)v;
                else           ((long long*)tail)[b] = (long long)v;
            }
        }
        return;
    }
    const int h  = z;
    const int n0 = blockIdx.x * 128;
    const int m_begin = g_off[h] + blockIdx.y * 64;
    const int m_end   = g_off[h + 1];
    if (m_begin >= m_end) return;

    __shared__ __align__(16) char sm[3][STAGE_B];

    const int tid  = threadIdx.x;
    const int lane = tid & 31;
    const int wid  = tid >> 5;
    const int wm   = wid & 1;          // 2 warps over M (32 rows each)
    const int wn   = wid >> 1;         // 2 warps over N (64 cols each)

    float acc[2][8][4];
#pragma unroll
    for (int mi = 0; mi < 2; mi++)
#pragma unroll
        for (int ni = 0; ni < 8; ni++)
#pragma unroll
            for (int e = 0; e < 4; e++) acc[mi][ni][e] = 0.0f;

    // cp.async coordinates:
    //   A: 64 rows x 2 16B-segs per plane = 128 cp16 -> 1/thread/plane
    //   B: 16 rows x 16 segs per plane    = 256 cp16 -> 2/thread/plane
    const int arow = tid >> 1, aseg = tid & 1;

    const __nv_bfloat16* aRow;   // this thread's A source (hi at +kk, lo at +512+kk)
    {
        int p = m_begin + arow;
        if (p > Bn - 1) p = Bn - 1;
        aRow = g_A + (size_t)g_rows[p] * KPACK + aseg * 8;
    }
    const __nv_bfloat16* bHi = g_Bw + ((size_t)(h * 2 + 0) * IN_DIM) * OUT_DIM + n0;
    const __nv_bfloat16* bLo = g_Bw + ((size_t)(h * 2 + 1) * IN_DIM) * OUT_DIM + n0;

    auto load_chunk = [&](int c, int stg) {
        const int kk = c << 4;
        const uint32_t sB = smem_u32(&sm[stg][0]);
        cpasync16(sB + OFF_AHI + arow * A_STRIDE_B + aseg * 16, aRow + kk);
        cpasync16(sB + OFF_ALO + arow * A_STRIDE_B + aseg * 16, aRow + 512 + kk);
#pragma unroll
        for (int i = 0; i < 2; i++) {
            int idx = tid + i * 128;
            int row = idx >> 4, seg = idx & 15;
            cpasync16(sB + OFF_BHI + row * B_STRIDE_B + seg * 16,
                      bHi + (size_t)(kk + row) * OUT_DIM + seg * 8);
            cpasync16(sB + OFF_BLO + row * B_STRIDE_B + seg * 16,
                      bLo + (size_t)(kk + row) * OUT_DIM + seg * 8);
        }
        CP_COMMIT();
    };

    load_chunk(0, 0);
    load_chunk(1, 1);

    for (int c = 0; c < NCHUNK; c++) {
        if (c + 1 < NCHUNK) CP_WAIT1();   // pending {c,c+1} -> drains c
        else                CP_WAIT0();   // last chunk: full drain
        __syncthreads();

        if (c + 2 < NCHUNK) load_chunk(c + 2, (c + 2) % 3);

        const int stg = c % 3;
        const uint32_t sB = smem_u32(&sm[stg][0]);

        // A fragments, both planes (k16 -> one ldmatrix.x4 per mi per plane)
        uint32_t ahi[2][4], alo[2][4];
#pragma unroll
        for (int mi = 0; mi < 2; mi++) {
            int row = wm * 32 + mi * 16 + (lane & 15);
            uint32_t off = row * A_STRIDE_B + ((lane >> 4) & 1) * 16;
            asm volatile("ldmatrix.sync.aligned.m8n8.x4.shared.b16 {%0,%1,%2,%3}, [%4];"
                : "=r"(ahi[mi][0]), "=r"(ahi[mi][1]), "=r"(ahi[mi][2]), "=r"(ahi[mi][3])
                : "r"(sB + OFF_AHI + off));
            asm volatile("ldmatrix.sync.aligned.m8n8.x4.shared.b16 {%0,%1,%2,%3}, [%4];"
                : "=r"(alo[mi][0]), "=r"(alo[mi][1]), "=r"(alo[mi][2]), "=r"(alo[mi][3])
                : "r"(sB + OFF_ALO + off));
        }

        const int krow = (lane & 7) + ((lane >> 3) & 1) * 8;
        const int ncb  = wn * 64 + ((lane >> 4) & 1) * 8;

        uint32_t b[8][2];
        // B hi plane -> passes 1 (hi*hi) and 2 (lo*hi)
#pragma unroll
        for (int g = 0; g < 4; g++) {
            uint32_t addr = sB + OFF_BHI + krow * B_STRIDE_B + (ncb + g * 16) * 2;
            asm volatile("ldmatrix.sync.aligned.m8n8.x4.trans.shared.b16 {%0,%1,%2,%3}, [%4];"
                : "=r"(b[g * 2][0]), "=r"(b[g * 2][1]),
                  "=r"(b[g * 2 + 1][0]), "=r"(b[g * 2 + 1][1])
                : "r"(addr));
        }
#pragma unroll
        for (int mi = 0; mi < 2; mi++)
#pragma unroll
            for (int ni = 0; ni < 8; ni++) {
                asm volatile(
                    "mma.sync.aligned.m16n8k16.row.col.f32.bf16.bf16.f32 "
                    "{%0,%1,%2,%3}, {%4,%5,%6,%7}, {%8,%9}, {%0,%1,%2,%3};"
                    : "+f"(acc[mi][ni][0]), "+f"(acc[mi][ni][1]),
                      "+f"(acc[mi][ni][2]), "+f"(acc[mi][ni][3])
                    : "r"(ahi[mi][0]), "r"(ahi[mi][1]), "r"(ahi[mi][2]), "r"(ahi[mi][3]),
                      "r"(b[ni][0]), "r"(b[ni][1]));
                asm volatile(
                    "mma.sync.aligned.m16n8k16.row.col.f32.bf16.bf16.f32 "
                    "{%0,%1,%2,%3}, {%4,%5,%6,%7}, {%8,%9}, {%0,%1,%2,%3};"
                    : "+f"(acc[mi][ni][0]), "+f"(acc[mi][ni][1]),
                      "+f"(acc[mi][ni][2]), "+f"(acc[mi][ni][3])
                    : "r"(alo[mi][0]), "r"(alo[mi][1]), "r"(alo[mi][2]), "r"(alo[mi][3]),
                      "r"(b[ni][0]), "r"(b[ni][1]));
            }
        // B lo plane -> pass 3 (hi*lo), reuse b regs
#pragma unroll
        for (int g = 0; g < 4; g++) {
            uint32_t addr = sB + OFF_BLO + krow * B_STRIDE_B + (ncb + g * 16) * 2;
            asm volatile("ldmatrix.sync.aligned.m8n8.x4.trans.shared.b16 {%0,%1,%2,%3}, [%4];"
                : "=r"(b[g * 2][0]), "=r"(b[g * 2][1]),
                  "=r"(b[g * 2 + 1][0]), "=r"(b[g * 2 + 1][1])
                : "r"(addr));
        }
#pragma unroll
        for (int mi = 0; mi < 2; mi++)
#pragma unroll
            for (int ni = 0; ni < 8; ni++) {
                asm volatile(
                    "mma.sync.aligned.m16n8k16.row.col.f32.bf16.bf16.f32 "
                    "{%0,%1,%2,%3}, {%4,%5,%6,%7}, {%8,%9}, {%0,%1,%2,%3};"
                    : "+f"(acc[mi][ni][0]), "+f"(acc[mi][ni][1]),
                      "+f"(acc[mi][ni][2]), "+f"(acc[mi][ni][3])
                    : "r"(ahi[mi][0]), "r"(ahi[mi][1]), "r"(ahi[mi][2]), "r"(ahi[mi][3]),
                      "r"(b[ni][0]), "r"(b[ni][1]));
            }
    }

    // Epilogue: direct store with bias (full K per block -> no reduction).
    // row = wm*32 + mi*16 + rp*8 + (lane>>2), col = wn*64 + ni*8 + (lane&3)*2
#pragma unroll
    for (int mi = 0; mi < 2; mi++) {
#pragma unroll
        for (int rp = 0; rp < 2; rp++) {
            int r = wm * 32 + mi * 16 + rp * 8 + (lane >> 2);
            int p = m_begin + r;
            if (p < m_end) {
                int bb = g_rows[p];
                float* op = out + (size_t)bb * OUT_DIM + n0 + wn * 64 + (lane & 3) * 2;
                const float* bp = bias + h * OUT_DIM + n0 + wn * 64 + (lane & 3) * 2;
#pragma unroll
                for (int ni = 0; ni < 8; ni++) {
                    float2 r2;
                    r2.x = acc[mi][ni][rp * 2 + 0] + bp[ni * 8 + 0];
                    r2.y = acc[mi][ni][rp * 2 + 1] + bp[ni * 8 + 1];
                    *(float2*)(op + ni * 8) = r2;
                }
            }
        }
    }
}

extern "C" void kernel_launch(void* const* d_in, const int* in_sizes, int n_in,
                              void* d_out, int out_size) {
    const float* X     = (const float*)d_in[0];
    const int*   idx_w = (const int*)d_in[1];
    const float* W     = (const float*)d_in[2];
    const float* bias  = (const float*)d_in[3];
    float*       out   = (float*)d_out;

    const int Bn = in_sizes[1];

    const int XB = (Bn + 7) / 8;
    prep<<<1 + XB + 512, 256>>>(X, idx_w, W, Bn);

    long long extra = (long long)out_size - (long long)Bn * OUT_DIM;
    float* tail = nullptr;
    int mode = 0;
    if (extra >= Bn) {
        mode = (extra >= 2 * (long long)Bn) ? 2 : 1;
        tail = out + (size_t)Bn * OUT_DIM;
    }

    int m_slots = (Bn + 63) / 64;
    dim3 g(OUT_DIM / 128, m_slots, NHEADS + 1);
    gemm_mma<<<g, 128>>>(bias, out, Bn, idx_w, tail, mode);
}

// round 16
// speedup vs baseline: 1.2870x; 1.2870x over previous
#include <cuda_runtime.h>
#include <cuda_bf16.h>
#include <stdint.h>

// SelectiveLinear: out[b,:] = X[b,:] @ W[idx[b]] + bias[idx[b]]
// B=2048, IN=512, OUT=512, H=16.
// R16 = resubmission of R15 (bench infra failed twice; no kernel evidence).
// Fused 3-term mainloop (R14, ratio 0.75) + split-K 2-way (320 blocks,
// ~2.2/SM) -> dominates R10 (ratio 1.1, 3 atomics/elt) on all axes.
// 2 atomics/elt, out zeroed in prep, bias added by khalf==0 blocks.

#define IN_DIM  512
#define OUT_DIM 512
#define NHEADS  16
#define MAXB    2048
#define KPACK   1024            // g_A row: [hi(512) | lo(512)] bf16
#define NCHUNK_B 16             // k16 chunks per block (one K-half)
#define A_STRIDE_B 48           // A plane row stride: 32B data + 16B pad
#define B_STRIDE_B 272          // B plane row stride: 256B data + 16B pad
#define A_PL_B  (64 * A_STRIDE_B)     // 3072
#define B_PL_B  (16 * B_STRIDE_B)     // 4352
#define OFF_AHI 0
#define OFF_ALO (A_PL_B)              // 3072
#define OFF_BHI (2 * A_PL_B)          // 6144
#define OFF_BLO (2 * A_PL_B + B_PL_B) // 10496
#define STAGE_B (2 * A_PL_B + 2 * B_PL_B)  // 14848; 3 stages = 44544 < 48K

__device__ int g_rows[MAXB];
__device__ int g_off[NHEADS + 1];
__device__ int g_is64;
__device__ __align__(256) __nv_bfloat16 g_A[(size_t)MAXB * KPACK];                   // 4MB
__device__ __align__(256) __nv_bfloat16 g_Bw[(size_t)NHEADS * 2 * IN_DIM * OUT_DIM]; // 16MB

__device__ __forceinline__ uint32_t smem_u32(const void* p) {
    uint32_t a;
    asm("{ .reg .u64 t; cvta.to.shared.u64 t, %1; cvt.u32.u64 %0, t; }"
        : "=r"(a) : "l"(p));
    return a;
}
__device__ __forceinline__ void cpasync16(uint32_t dst, const void* src) {
    asm volatile("cp.async.cg.shared.global [%0], [%1], 16;" :: "r"(dst), "l"(src) : "memory");
}
#define CP_COMMIT() asm volatile("cp.async.commit_group;" ::: "memory")
#define CP_WAIT0()  asm volatile("cp.async.wait_group 0;" ::: "memory")
#define CP_WAIT1()  asm volatile("cp.async.wait_group 1;" ::: "memory")

__device__ __forceinline__ int load_idx(const int* __restrict__ w, int b, int is64) {
    return w[is64 ? (b << 1) : b];
}

// ---------------------------------------------------------------------------
// Kernel 1: prep.
//   bx == 0             : idx dtype sniff + bucket-by-head
//   bx in [1, XB]       : X -> bf16 hi|lo (at original row)
//   bx in (XB, XB+512]  : W -> bf16 hi|lo  [h][sel][k][n]
//   bx in (XB+512, +ZB] : zero out[0 .. Bn*OUT) (split-K accumulators)
// ---------------------------------------------------------------------------
__global__ __launch_bounds__(256)
void prep(const float* __restrict__ X, const int* __restrict__ idx_w,
          const float* __restrict__ W, float* __restrict__ out, int Bn) {
    const int bx = blockIdx.x;
    const int tid = threadIdx.x;
    const int XB = (Bn + 7) / 8;

    if (bx == 0) {
        __shared__ int s_not;
        __shared__ int s_cnt[NHEADS];
        __shared__ int s_base[NHEADS];
        if (tid == 0) s_not = 0;
        __syncthreads();
        for (int i = tid; i < Bn; i += 256) {
            int v = idx_w[i];
            if (i & 1) { if (v != 0) s_not = 1; }
            else       { if (v < 0 || v >= NHEADS) s_not = 1; }
        }
        __syncthreads();
        const int is64 = s_not ? 0 : 1;
        if (tid == 0) g_is64 = is64;
        if (tid < NHEADS) s_cnt[tid] = 0;
        __syncthreads();
        for (int b = tid; b < Bn; b += 256)
            atomicAdd(&s_cnt[load_idx(idx_w, b, is64) & (NHEADS - 1)], 1);
        __syncthreads();
        if (tid == 0) {
            int acc = 0;
            for (int h = 0; h < NHEADS; h++) { g_off[h] = acc; s_base[h] = acc; acc += s_cnt[h]; }
            g_off[NHEADS] = acc;
        }
        __syncthreads();
        for (int b = tid; b < Bn; b += 256) {
            int h = load_idx(idx_w, b, is64) & (NHEADS - 1);
            g_rows[atomicAdd(&s_base[h], 1)] = b;
        }
    } else if (bx <= XB) {
        int p = (bx - 1) * 8 + (tid >> 5);
        int l = tid & 31;
        if (p >= Bn) return;
        const float4* xr = (const float4*)(X + (size_t)p * IN_DIM);
        union { __nv_bfloat16 h[16]; uint4 u[2]; } hi, lo;
#pragma unroll
        for (int q = 0; q < 4; q++) {
            float4 v = xr[l * 4 + q];
            float f[4] = {v.x, v.y, v.z, v.w};
#pragma unroll
            for (int e = 0; e < 4; e++) {
                __nv_bfloat16 hv = __float2bfloat16(f[e]);
                hi.h[q * 4 + e] = hv;
                lo.h[q * 4 + e] = __float2bfloat16(f[e] - __bfloat162float(hv));
            }
        }
        uint4* dh = (uint4*)(g_A + (size_t)p * KPACK + l * 16);
        dh[0] = hi.u[0]; dh[1] = hi.u[1];
        uint4* dl = (uint4*)(g_A + (size_t)p * KPACK + 512 + l * 16);
        dl[0] = lo.u[0]; dl[1] = lo.u[1];
    } else if (bx <= XB + 512) {
        const int wb = bx - 1 - XB;
        const int total = NHEADS * IN_DIM * (OUT_DIM / 4);
#pragma unroll
        for (int i = 0; i < 8; i++) {
            int id = wb * 2048 + i * 256 + tid;
            if (id >= total) break;
            int h   = id / (IN_DIM * (OUT_DIM / 4));
            int rem = id % (IN_DIM * (OUT_DIM / 4));
            int k   = rem / (OUT_DIM / 4);
            int n4  = rem % (OUT_DIM / 4);
            float4 v = ((const float4*)W)[(size_t)id];
            float f[4] = {v.x, v.y, v.z, v.w};
            union { __nv_bfloat16 h[4]; uint2 u; } hi, lo;
#pragma unroll
            for (int e = 0; e < 4; e++) {
                __nv_bfloat16 hv = __float2bfloat16(f[e]);
                hi.h[e] = hv;
                lo.h[e] = __float2bfloat16(f[e] - __bfloat162float(hv));
            }
            size_t basehi = (((size_t)h * 2 + 0) * IN_DIM + k) * OUT_DIM + n4 * 4;
            size_t baselo = (((size_t)h * 2 + 1) * IN_DIM + k) * OUT_DIM + n4 * 4;
            *(uint2*)(g_Bw + basehi) = hi.u;
            *(uint2*)(g_Bw + baselo) = lo.u;
        }
    } else {
        const int zb = bx - 1 - XB - 512;
        const long long nf4 = (long long)Bn * OUT_DIM / 4;
        float4 z4 = make_float4(0.f, 0.f, 0.f, 0.f);
#pragma unroll
        for (int i = 0; i < 4; i++) {
            long long id = (long long)zb * 1024 + i * 256 + tid;
            if (id < nf4) ((float4*)out)[id] = z4;
        }
    }
}

// ---------------------------------------------------------------------------
// Kernel 2: fused 3-term GEMM, split-K 2-way, atomicAdd reduction + tail echo.
// grid (4 n-tiles, ceil(Bn/64) m-slots, 2*NHEADS+1), 128 threads (4 warps 2x2).
// Block tile M=64, N=128; warp tile 32x64; 16 chunks of k=16 (one K-half);
// each chunk loads Ahi|Alo|Bhi|Blo once, 3 MMA passes into one accumulator.
// ---------------------------------------------------------------------------
__global__ __launch_bounds__(128)
void gemm_mma(const float* __restrict__ bias, float* __restrict__ out, int Bn,
              const int* __restrict__ idx_w, float* __restrict__ tail, int mode) {
    const int z = blockIdx.z;
    if (z == 2 * NHEADS) {   // fused tail echo
        if (blockIdx.x == 0 && blockIdx.y == 0 && tail != nullptr) {
            const int is64 = g_is64;
            for (int b = threadIdx.x; b < Bn; b += 128) {
                int v = load_idx(idx_w, b, is64) & (NHEADS - 1);
                if (mode == 1) tail[b] = (float)v;
                else           ((long long*)tail)[b] = (long long)v;
            }
        }
        return;
    }
    const int khalf = z >> 4;         // 0 or 1
    const int h     = z & 15;
    const int n0    = blockIdx.x * 128;
    const int m_begin = g_off[h] + blockIdx.y * 64;
    const int m_end   = g_off[h + 1];
    if (m_begin >= m_end) return;

    __shared__ __align__(16) char sm[3][STAGE_B];

    const int tid  = threadIdx.x;
    const int lane = tid & 31;
    const int wid  = tid >> 5;
    const int wm   = wid & 1;          // 2 warps over M (32 rows each)
    const int wn   = wid >> 1;         // 2 warps over N (64 cols each)

    float acc[2][8][4];
#pragma unroll
    for (int mi = 0; mi < 2; mi++)
#pragma unroll
        for (int ni = 0; ni < 8; ni++)
#pragma unroll
            for (int e = 0; e < 4; e++) acc[mi][ni][e] = 0.0f;

    const int arow = tid >> 1, aseg = tid & 1;
    const int kbase = khalf * NCHUNK_B;   // chunk offset of this K-half

    const __nv_bfloat16* aRow;   // hi at +kk, lo at +512+kk
    {
        int p = m_begin + arow;
        if (p > Bn - 1) p = Bn - 1;
        aRow = g_A + (size_t)g_rows[p] * KPACK + aseg * 8;
    }
    const __nv_bfloat16* bHi = g_Bw + ((size_t)(h * 2 + 0) * IN_DIM) * OUT_DIM + n0;
    const __nv_bfloat16* bLo = g_Bw + ((size_t)(h * 2 + 1) * IN_DIM) * OUT_DIM + n0;

    auto load_chunk = [&](int c, int stg) {
        const int kk = (kbase + c) << 4;
        const uint32_t sB = smem_u32(&sm[stg][0]);
        cpasync16(sB + OFF_AHI + arow * A_STRIDE_B + aseg * 16, aRow + kk);
        cpasync16(sB + OFF_ALO + arow * A_STRIDE_B + aseg * 16, aRow + 512 + kk);
#pragma unroll
        for (int i = 0; i < 2; i++) {
            int idx = tid + i * 128;
            int row = idx >> 4, seg = idx & 15;
            cpasync16(sB + OFF_BHI + row * B_STRIDE_B + seg * 16,
                      bHi + (size_t)(kk + row) * OUT_DIM + seg * 8);
            cpasync16(sB + OFF_BLO + row * B_STRIDE_B + seg * 16,
                      bLo + (size_t)(kk + row) * OUT_DIM + seg * 8);
        }
        CP_COMMIT();
    };

    load_chunk(0, 0);
    load_chunk(1, 1);

    for (int c = 0; c < NCHUNK_B; c++) {
        if (c + 1 < NCHUNK_B) CP_WAIT1();   // pending {c,c+1} -> drains c
        else                  CP_WAIT0();   // last chunk: full drain
        __syncthreads();

        if (c + 2 < NCHUNK_B) load_chunk(c + 2, (c + 2) % 3);

        const int stg = c % 3;
        const uint32_t sB = smem_u32(&sm[stg][0]);

        // A fragments, both planes
        uint32_t ahi[2][4], alo[2][4];
#pragma unroll
        for (int mi = 0; mi < 2; mi++) {
            int row = wm * 32 + mi * 16 + (lane & 15);
            uint32_t off = row * A_STRIDE_B + ((lane >> 4) & 1) * 16;
            asm volatile("ldmatrix.sync.aligned.m8n8.x4.shared.b16 {%0,%1,%2,%3}, [%4];"
                : "=r"(ahi[mi][0]), "=r"(ahi[mi][1]), "=r"(ahi[mi][2]), "=r"(ahi[mi][3])
                : "r"(sB + OFF_AHI + off));
            asm volatile("ldmatrix.sync.aligned.m8n8.x4.shared.b16 {%0,%1,%2,%3}, [%4];"
                : "=r"(alo[mi][0]), "=r"(alo[mi][1]), "=r"(alo[mi][2]), "=r"(alo[mi][3])
                : "r"(sB + OFF_ALO + off));
        }

        const int krow = (lane & 7) + ((lane >> 3) & 1) * 8;
        const int ncb  = wn * 64 + ((lane >> 4) & 1) * 8;

        uint32_t b[8][2];
        // B hi plane -> passes 1 (hi*hi) and 2 (lo*hi)
#pragma unroll
        for (int g = 0; g < 4; g++) {
            uint32_t addr = sB + OFF_BHI + krow * B_STRIDE_B + (ncb + g * 16) * 2;
            asm volatile("ldmatrix.sync.aligned.m8n8.x4.trans.shared.b16 {%0,%1,%2,%3}, [%4];"
                : "=r"(b[g * 2][0]), "=r"(b[g * 2][1]),
                  "=r"(b[g * 2 + 1][0]), "=r"(b[g * 2 + 1][1])
                : "r"(addr));
        }
#pragma unroll
        for (int mi = 0; mi < 2; mi++)
#pragma unroll
            for (int ni = 0; ni < 8; ni++) {
                asm volatile(
                    "mma.sync.aligned.m16n8k16.row.col.f32.bf16.bf16.f32 "
                    "{%0,%1,%2,%3}, {%4,%5,%6,%7}, {%8,%9}, {%0,%1,%2,%3};"
                    : "+f"(acc[mi][ni][0]), "+f"(acc[mi][ni][1]),
                      "+f"(acc[mi][ni][2]), "+f"(acc[mi][ni][3])
                    : "r"(ahi[mi][0]), "r"(ahi[mi][1]), "r"(ahi[mi][2]), "r"(ahi[mi][3]),
                      "r"(b[ni][0]), "r"(b[ni][1]));
                asm volatile(
                    "mma.sync.aligned.m16n8k16.row.col.f32.bf16.bf16.f32 "
                    "{%0,%1,%2,%3}, {%4,%5,%6,%7}, {%8,%9}, {%0,%1,%2,%3};"
                    : "+f"(acc[mi][ni][0]), "+f"(acc[mi][ni][1]),
                      "+f"(acc[mi][ni][2]), "+f"(acc[mi][ni][3])
                    : "r"(alo[mi][0]), "r"(alo[mi][1]), "r"(alo[mi][2]), "r"(alo[mi][3]),
                      "r"(b[ni][0]), "r"(b[ni][1]));
            }
        // B lo plane -> pass 3 (hi*lo)
#pragma unroll
        for (int g = 0; g < 4; g++) {
            uint32_t addr = sB + OFF_BLO + krow * B_STRIDE_B + (ncb + g * 16) * 2;
            asm volatile("ldmatrix.sync.aligned.m8n8.x4.trans.shared.b16 {%0,%1,%2,%3}, [%4];"
                : "=r"(b[g * 2][0]), "=r"(b[g * 2][1]),
                  "=r"(b[g * 2 + 1][0]), "=r"(b[g * 2 + 1][1])
                : "r"(addr));
        }
#pragma unroll
        for (int mi = 0; mi < 2; mi++)
#pragma unroll
            for (int ni = 0; ni < 8; ni++) {
                asm volatile(
                    "mma.sync.aligned.m16n8k16.row.col.f32.bf16.bf16.f32 "
                    "{%0,%1,%2,%3}, {%4,%5,%6,%7}, {%8,%9}, {%0,%1,%2,%3};"
                    : "+f"(acc[mi][ni][0]), "+f"(acc[mi][ni][1]),
                      "+f"(acc[mi][ni][2]), "+f"(acc[mi][ni][3])
                    : "r"(ahi[mi][0]), "r"(ahi[mi][1]), "r"(ahi[mi][2]), "r"(ahi[mi][3]),
                      "r"(b[ni][0]), "r"(b[ni][1]));
            }
    }

    // Epilogue: atomicAdd partials into prep-zeroed out; bias by khalf==0.
    const bool addb = (khalf == 0);
#pragma unroll
    for (int mi = 0; mi < 2; mi++) {
#pragma unroll
        for (int rp = 0; rp < 2; rp++) {
            int r = wm * 32 + mi * 16 + rp * 8 + (lane >> 2);
            int p = m_begin + r;
            if (p < m_end) {
                int bb = g_rows[p];
                float* op = out + (size_t)bb * OUT_DIM + n0 + wn * 64 + (lane & 3) * 2;
                const float* bp = bias + h * OUT_DIM + n0 + wn * 64 + (lane & 3) * 2;
#pragma unroll
                for (int ni = 0; ni < 8; ni++) {
                    float v0 = acc[mi][ni][rp * 2 + 0];
                    float v1 = acc[mi][ni][rp * 2 + 1];
                    if (addb) { v0 += bp[ni * 8 + 0]; v1 += bp[ni * 8 + 1]; }
                    atomicAdd(op + ni * 8 + 0, v0);
                    atomicAdd(op + ni * 8 + 1, v1);
                }
            }
        }
    }
}

extern "C" void kernel_launch(void* const* d_in, const int* in_sizes, int n_in,
                              void* d_out, int out_size) {
    const float* X     = (const float*)d_in[0];
    const int*   idx_w = (const int*)d_in[1];
    const float* W     = (const float*)d_in[2];
    const float* bias  = (const float*)d_in[3];
    float*       out   = (float*)d_out;

    const int Bn = in_sizes[1];

    const int XB = (Bn + 7) / 8;
    const int ZB = (int)(((long long)Bn * OUT_DIM / 4 + 1023) / 1024);
    prep<<<1 + XB + 512 + ZB, 256>>>(X, idx_w, W, out, Bn);

    long long extra = (long long)out_size - (long long)Bn * OUT_DIM;
    float* tail = nullptr;
    int mode = 0;
    if (extra >= Bn) {
        mode = (extra >= 2 * (long long)Bn) ? 2 : 1;
        tail = out + (size_t)Bn * OUT_DIM;
    }

    int m_slots = (Bn + 63) / 64;
    dim3 g(OUT_DIM / 128, m_slots, 2 * NHEADS + 1);
    gemm_mma<<<g, 128>>>(bias, out, Bn, idx_w, tail, mode);
}